// round 16
// baseline (speedup 1.0000x reference)
#include <cuda_runtime.h>
#include <cuda_fp16.h>
#include <math.h>
#include <stdint.h>

#define S_LEN 4096
#define NH 8
#define NKV 4
#define HD 256

// ---------------- scratch (allocation-free device globals) -----------------
__device__ __half g_q[(size_t)NH * S_LEN * HD];     // [h][s][d] fp16
__device__ __half g_k[(size_t)NKV * S_LEN * HD];    // [h][s][d] fp16
__device__ __half g_vt[(size_t)NKV * HD * S_LEN];   // [h][d][s] fp16 (transposed)
__device__ __half g_attn[(size_t)S_LEN * 2048];     // [s][h*HD+d] fp16
__device__ __half g_ah[(size_t)S_LEN * 2048];       // hs fp16
__device__ __half g_wqt[(size_t)2048 * 2048];       // weights [N][K] fp16
__device__ __half g_wkt[(size_t)1024 * 2048];
__device__ __half g_wvt[(size_t)1024 * 2048];
__device__ __half g_wot[(size_t)2048 * 2048];
__device__ double g_invd[128];                      // rope inv_freq table

__device__ __forceinline__ uint32_t cvta_shared(const void* p) {
    uint32_t a;
    asm("{ .reg .u64 t; cvta.to.shared.u64 t, %1; cvt.u32.u64 %0, t; }"
        : "=r"(a) : "l"(p));
    return a;
}

__device__ __forceinline__ void cp16(uint32_t dst, const void* src) {
    asm volatile("cp.async.cg.shared.global [%0], [%1], 16;"
                 :: "r"(dst), "l"(src));
}
#define CP_COMMIT() asm volatile("cp.async.commit_group;")
#define CP_WAIT0()  asm volatile("cp.async.wait_group 0;")
#define CP_WAIT1()  asm volatile("cp.async.wait_group 1;")

#define MMA_F16(C, A, B0, B1)                                               \
    asm volatile(                                                           \
        "mma.sync.aligned.m16n8k16.row.col.f32.f16.f16.f32 "                \
        "{%0,%1,%2,%3}, {%4,%5,%6,%7}, {%8,%9}, {%0,%1,%2,%3};"             \
        : "+f"((C)[0]), "+f"((C)[1]), "+f"((C)[2]), "+f"((C)[3])            \
        : "r"((A)[0]), "r"((A)[1]), "r"((A)[2]), "r"((A)[3]),               \
          "r"(B0), "r"(B1))

#define LDSM4(R, addr)                                                      \
    asm volatile("ldmatrix.sync.aligned.m8n8.x4.shared.b16 "                \
                 "{%0,%1,%2,%3}, [%4];"                                     \
        : "=r"((R)[0]), "=r"((R)[1]), "=r"((R)[2]), "=r"((R)[3])            \
        : "r"(addr))

__device__ __forceinline__ uint32_t pack2(float a, float b) {
    __half2 h = __floats2half2_rn(a, b);
    return *(uint32_t*)&h;
}

// ---------------------------------------------------------------------------
__global__ void invd_kernel()
{
    int i = threadIdx.x;
    g_invd[i] = exp(-(double)i * (9.210340371976184 / 128.0));
}

__global__ void tohalf_kernel(const float* __restrict__ src,
                              __half* __restrict__ dst, int n8)
{
    int i = blockIdx.x * blockDim.x + threadIdx.x;
    if (i >= n8) return;
    float4 a = ((const float4*)src)[i * 2];
    float4 b = ((const float4*)src)[i * 2 + 1];
    uint4 o;
    o.x = pack2(a.x, a.y); o.y = pack2(a.z, a.w);
    o.z = pack2(b.x, b.y); o.w = pack2(b.z, b.w);
    ((uint4*)dst)[i] = o;
}

__global__ void thalf_all_kernel(const float* __restrict__ wq,
                                 const float* __restrict__ wk,
                                 const float* __restrict__ wv,
                                 const float* __restrict__ wo,
                                 __half* __restrict__ wqt,
                                 __half* __restrict__ wkt,
                                 __half* __restrict__ wvt,
                                 __half* __restrict__ wot)
{
    __shared__ float t[32][33];
    const int bx = blockIdx.x;
    const float* W;
    __half* Wt;
    int N, n0;
    if (bx < 64)       { W = wq; Wt = wqt; N = 2048; n0 = bx * 32; }
    else if (bx < 96)  { W = wk; Wt = wkt; N = 1024; n0 = (bx - 64) * 32; }
    else if (bx < 128) { W = wv; Wt = wvt; N = 1024; n0 = (bx - 96) * 32; }
    else               { W = wo; Wt = wot; N = 2048; n0 = (bx - 128) * 32; }
    const int k0 = blockIdx.y * 32;
    const int tx = threadIdx.x, ty = threadIdx.y;
#pragma unroll
    for (int j = 0; j < 4; j++)
        t[ty + 8 * j][tx] = W[(size_t)(k0 + ty + 8 * j) * N + n0 + tx];
    __syncthreads();
    const int nl = ty * 4 + (tx >> 3);
    const int kl = (tx & 7) * 4;
    uint2 o;
    o.x = pack2(t[kl + 0][nl], t[kl + 1][nl]);
    o.y = pack2(t[kl + 2][nl], t[kl + 3][nl]);
    *(uint2*)&Wt[(size_t)(n0 + nl) * 2048 + k0 + kl] = o;
}

// ---------------------------------------------------------------------------
// fp16 tensor-core GEMM, ldmatrix fragments, 3-stage cp.async pipeline.
// C[M,N] = A[M,2048] @ Wt[N,2048]^T, 128x128 tile, BK=64, 8 warps (4m x 2n).
// ---------------------------------------------------------------------------
#define GH_PLANE 18432                   // 128 rows * 144 B
#define GH_STAGE (2 * GH_PLANE)
#define GH_SMEM  (3 * GH_STAGE)          // 110592 B (3 stages)

__global__ __launch_bounds__(256, 2) void gemm_h_kernel(
    const __half* __restrict__ A,
    const __half* __restrict__ B0t, const __half* __restrict__ B1t,
    const __half* __restrict__ B2t,
    __half* __restrict__ Cq, __half* __restrict__ Ck, __half* __restrict__ Cvt,
    float* __restrict__ Cplain, int merged)
{
    extern __shared__ char gsm[];
    const uint32_t smem_base = cvta_shared(gsm);

    const int tid  = threadIdx.x;
    const int lane = tid & 31;
    const int wid  = tid >> 5;
    const int wm   = (wid & 3) * 32;
    const int wn   = (wid >> 2) * 64;
    const int bm   = blockIdx.y * 128;
    const int bn   = blockIdx.x * 128;
    const int grp  = lane >> 2;
    const int qd   = lane & 3;
    const int mi   = lane >> 3;
    const int r8   = lane & 7;

    const uint32_t aoff = (uint32_t)(wm + (mi & 1) * 8 + r8) * 144 + (mi >> 1) * 16;
    const uint32_t boff = (uint32_t)GH_PLANE +
                          (uint32_t)(wn + (mi >> 1) * 8 + r8) * 144 + (mi & 1) * 16;

    const __half* Bt;
    int nb, head = 0, colb0 = 0, region = 0;
    if (merged) {
        if (bn < 2048)      { Bt = B0t; nb = bn;        region = 0; }
        else if (bn < 3072) { Bt = B1t; nb = bn - 2048; region = 1; }
        else                { Bt = B2t; nb = bn - 3072; region = 2; }
        head = nb >> 8;
        colb0 = nb & 255;
    } else {
        Bt = B0t; nb = bn;
    }

    auto load_stage = [&](int chunk, int st) {
        const int k0 = chunk * 64;
        const uint32_t sb = smem_base + st * GH_STAGE;
#pragma unroll
        for (int p = 0; p < 4; p++) {
            int idx = tid + p * 256;
            int row = idx >> 3, c = idx & 7;
            cp16(sb + row * 144 + c * 16,
                 &A[(size_t)(bm + row) * 2048 + k0 + c * 8]);
            cp16(sb + GH_PLANE + row * 144 + c * 16,
                 &Bt[(size_t)(nb + row) * 2048 + k0 + c * 8]);
        }
        CP_COMMIT();
    };

    float c[2][8][4];
#pragma unroll
    for (int mf = 0; mf < 2; mf++)
#pragma unroll
        for (int nt = 0; nt < 8; nt++)
#pragma unroll
            for (int r = 0; r < 4; r++) c[mf][nt][r] = 0.f;

    load_stage(0, 0);
    load_stage(1, 1);

    int st = 0, ldst = 2;
    for (int i = 0; i < 32; i++) {
        if (i < 30) CP_WAIT1(); else CP_WAIT0();
        __syncthreads();
        if (i + 2 < 32) load_stage(i + 2, ldst);

        const uint32_t stb = smem_base + st * GH_STAGE;
#pragma unroll
        for (int s = 0; s < 4; s++) {
            uint32_t a[2][4];
            LDSM4(a[0], stb + aoff + s * 32);
            LDSM4(a[1], stb + aoff + 16 * 144 + s * 32);
#pragma unroll
            for (int ntp = 0; ntp < 4; ntp++) {
                uint32_t b[4];
                LDSM4(b, stb + boff + ntp * (16 * 144) + s * 32);
                MMA_F16(c[0][2 * ntp],     a[0], b[0], b[1]);
                MMA_F16(c[1][2 * ntp],     a[1], b[0], b[1]);
                MMA_F16(c[0][2 * ntp + 1], a[0], b[2], b[3]);
                MMA_F16(c[1][2 * ntp + 1], a[1], b[2], b[3]);
            }
        }
        __syncthreads();
        st   = (st == 2)   ? 0 : st + 1;
        ldst = (ldst == 2) ? 0 : ldst + 1;
    }

    const int m0 = bm + wm + grp;
    const int n0 = wn + 2 * qd;
    if (merged) {
        if (region < 2) {
            __half* Cp = (region == 0) ? Cq : Ck;
            const size_t hbase = (size_t)head * ((size_t)S_LEN * HD) + colb0;
#pragma unroll
            for (int mf = 0; mf < 2; mf++)
#pragma unroll
                for (int nt = 0; nt < 8; nt++) {
                    int m = m0 + mf * 16;
                    int ncol = n0 + nt * 8;
                    *(uint32_t*)&Cp[hbase + (size_t)m * HD + ncol] =
                        pack2(c[mf][nt][0], c[mf][nt][1]);
                    *(uint32_t*)&Cp[hbase + (size_t)(m + 8) * HD + ncol] =
                        pack2(c[mf][nt][2], c[mf][nt][3]);
                }
        } else {
            const size_t vbase = (size_t)head * ((size_t)HD * S_LEN);
#pragma unroll
            for (int mf = 0; mf < 2; mf++)
#pragma unroll
                for (int nt = 0; nt < 8; nt++) {
                    int m = m0 + mf * 16;
                    int d = colb0 + n0 + nt * 8;
                    Cvt[vbase + (size_t)d * S_LEN + m]           = __float2half_rn(c[mf][nt][0]);
                    Cvt[vbase + (size_t)(d + 1) * S_LEN + m]     = __float2half_rn(c[mf][nt][1]);
                    Cvt[vbase + (size_t)d * S_LEN + m + 8]       = __float2half_rn(c[mf][nt][2]);
                    Cvt[vbase + (size_t)(d + 1) * S_LEN + m + 8] = __float2half_rn(c[mf][nt][3]);
                }
        }
    } else {
#pragma unroll
        for (int mf = 0; mf < 2; mf++)
#pragma unroll
            for (int nt = 0; nt < 8; nt++) {
                int m = m0 + mf * 16;
                int n = bn + n0 + nt * 8;
                *(float2*)&Cplain[(size_t)m * 2048 + n] =
                    make_float2(c[mf][nt][0], c[mf][nt][1]);
                *(float2*)&Cplain[(size_t)(m + 8) * 2048 + n] =
                    make_float2(c[mf][nt][2], c[mf][nt][3]);
            }
    }
}

// ---------------------------------------------------------------------------
// RoPE on fp16 q/k (table inv_freq, DMUL range reduction).
// ---------------------------------------------------------------------------
__global__ void rope_kernel(const void* __restrict__ pos_raw)
{
    int idx = blockIdx.x * blockDim.x + threadIdx.x;
    if (idx >= S_LEN * 128) return;
    int i = idx & 127;
    int s = idx >> 7;

    const int* p32 = (const int*)pos_raw;
    long long pll = (p32[1] == 0) ? ((const long long*)pos_raw)[s]
                                  : (long long)p32[s];
    float p = (float)pll;

    float f = (float)((double)p * g_invd[i]);
    const double TWO_PI     = 6.283185307179586476925287;
    const double INV_TWO_PI = 0.15915494309189533576888;
    double r = (double)f;
    r -= TWO_PI * floor(r * INV_TWO_PI);
    float sv = sinf((float)r);
    float cv = cosf((float)r);

#pragma unroll
    for (int h = 0; h < NH; h++) {
        __half* base = g_q + ((size_t)h * S_LEN + s) * HD;
        float x1 = __half2float(base[i]), x2 = __half2float(base[i + 128]);
        base[i]       = __float2half_rn((x1 * cv - x2 * sv) * 0.0625f);
        base[i + 128] = __float2half_rn((x2 * cv + x1 * sv) * 0.0625f);
    }
#pragma unroll
    for (int h = 0; h < NKV; h++) {
        __half* base = g_k + ((size_t)h * S_LEN + s) * HD;
        float x1 = __half2float(base[i]), x2 = __half2float(base[i + 128]);
        base[i]       = __float2half_rn(x1 * cv - x2 * sv);
        base[i + 128] = __float2half_rn(x2 * cv + x1 * sv);
    }
}

// ---------------------------------------------------------------------------
// fp16 flash attention, warp-local rows (FA2 style) + rescale-skip vote.
// 8 warps x 16 q-rows; warp computes full 64 k-cols and 256 d-cols.
// P in registers, single barrier per k-block, double-buffered K/V.
// Grid (16, 8) paired q-tiles (qt & 31-qt, 128 rows each), 66 k-blocks.
// ---------------------------------------------------------------------------
#define A2OFF_Q   0
#define A2_QSZ    (128 * 528)             // 67584
#define A2_KSZ    (64 * 528)              // 33792
#define A2_VSZ    (256 * 144)             // 36864
#define A2_STG(st) (A2_QSZ + (st) * (A2_KSZ + A2_VSZ))
#define ATTN_SMEM (A2_QSZ + 2 * (A2_KSZ + A2_VSZ))   // 208896

__global__ __launch_bounds__(256) void attn_h_kernel()
{
    extern __shared__ char smn[];
    const uint32_t sb = cvta_shared(smn);

    const int h  = blockIdx.y;
    const int hk = h >> 1;
    const int tid  = threadIdx.x;
    const int lane = tid & 31;
    const int wid  = tid >> 5;
    const int wm   = wid * 16;            // warp's 16 q-rows
    const int grp  = lane >> 2;
    const int qd   = lane & 3;
    const int mi   = lane >> 3;
    const int r8   = lane & 7;

    const uint32_t qBase = sb + A2OFF_Q +
        (uint32_t)(wm + (mi & 1) * 8 + r8) * 528 + (mi >> 1) * 16;
    const uint32_t kLane = (uint32_t)((mi >> 1) * 8 + r8) * 528 + (mi & 1) * 16;
    const uint32_t vLane = (uint32_t)((mi >> 1) * 8 + r8) * 144 + (mi & 1) * 16;

    const __half* Qh  = g_q  + (size_t)h  * S_LEN * HD;
    const __half* Kh  = g_k  + (size_t)hk * S_LEN * HD;
    const __half* Vth = g_vt + (size_t)hk * HD * S_LEN;

    const float LOG2E = 1.4426950408889634f;

    auto load_kv = [&](int k0, int st) {
        const uint32_t kb = sb + A2_STG(st);
        const uint32_t vb = kb + A2_KSZ;
#pragma unroll
        for (int p = 0; p < 8; p++) {
            int idx = tid + p * 256;
            int row = idx >> 5, cc = idx & 31;
            cp16(kb + row * 528 + cc * 16,
                 &Kh[(size_t)(k0 + row) * HD + cc * 8]);
        }
#pragma unroll
        for (int p = 0; p < 8; p++) {
            int idx = tid + p * 256;
            int row = idx >> 3, cc = idx & 7;
            cp16(vb + row * 144 + cc * 16,
                 &Vth[(size_t)row * S_LEN + k0 + cc * 8]);
        }
        CP_COMMIT();
    };

    for (int half = 0; half < 2; half++) {
        const int qt = half ? (31 - blockIdx.x) : blockIdx.x;
        const int q0 = qt * 128;
        const int nkb = 2 * qt + 2;

        __syncthreads();   // previous tile's compute done before restaging
#pragma unroll
        for (int p = 0; p < 16; p++) {
            int idx = tid + p * 256;
            int row = idx >> 5, cc = idx & 31;
            cp16(sb + A2OFF_Q + row * 528 + cc * 16,
                 &Qh[(size_t)(q0 + row) * HD + cc * 8]);
        }
        CP_COMMIT();
        load_kv(0, 0);

        float m0 = -3.0e38f, m1 = -3.0e38f, l0 = 0.f, l1 = 0.f;
        float o[32][4];
#pragma unroll
        for (int dt = 0; dt < 32; dt++)
#pragma unroll
            for (int r = 0; r < 4; r++) o[dt][r] = 0.f;

        for (int kb = 0; kb < nkb; kb++) {
            const int st = kb & 1;
            const int k0 = kb * 64;
            CP_WAIT0();
            __syncthreads();           // single barrier per k-block
            if (kb + 1 < nkb) load_kv(k0 + 64, st ^ 1);

            const uint32_t kBase = sb + A2_STG(st) + kLane;
            const uint32_t vBase = sb + A2_STG(st) + A2_KSZ + vLane;

            // ---- QK: 16 rows x 64 cols ----
            float s[8][4];
#pragma unroll
            for (int nt = 0; nt < 8; nt++)
#pragma unroll
                for (int r = 0; r < 4; r++) s[nt][r] = 0.f;
#pragma unroll 4
            for (int ks = 0; ks < 16; ks++) {
                uint32_t a[4];
                LDSM4(a, qBase + ks * 32);
#pragma unroll
                for (int t = 0; t < 4; t++) {
                    uint32_t b[4];
                    LDSM4(b, kBase + t * (16 * 528) + ks * 32);
                    MMA_F16(s[2 * t],     a, b[0], b[1]);
                    MMA_F16(s[2 * t + 1], a, b[2], b[3]);
                }
            }

            // ---- softcap + causal + warp-local softmax ----
            float lm0 = -3.0e38f, lm1 = -3.0e38f;
#pragma unroll
            for (int nt = 0; nt < 8; nt++)
#pragma unroll
                for (int cc = 0; cc < 4; cc++) {
                    float x = s[nt][cc];
                    float u = x * 0.02f;
                    float u2 = u * u;
                    float val = x * (1.f + u2 * (-0.333333333f +
                                  u2 * (0.133333333f + u2 * -0.053968254f)));
                    if (u2 > 0.1225f) val = 50.f * tanhf(u);
                    int kcol = k0 + nt * 8 + 2 * qd + (cc & 1);
                    int qrow = q0 + wm + grp + (cc >> 1) * 8;
                    if (kcol > qrow) val = -1.0e30f;
                    s[nt][cc] = val;
                    if (cc < 2) lm0 = fmaxf(lm0, val);
                    else        lm1 = fmaxf(lm1, val);
                }
            lm0 = fmaxf(lm0, __shfl_xor_sync(0xffffffffu, lm0, 1));
            lm0 = fmaxf(lm0, __shfl_xor_sync(0xffffffffu, lm0, 2));
            lm1 = fmaxf(lm1, __shfl_xor_sync(0xffffffffu, lm1, 1));
            lm1 = fmaxf(lm1, __shfl_xor_sync(0xffffffffu, lm1, 2));
            float mn0 = fmaxf(m0, lm0), mn1 = fmaxf(m1, lm1);
            float rc0 = exp2f((m0 - mn0) * LOG2E);
            float rc1 = exp2f((m1 - mn1) * LOG2E);
            m0 = mn0; m1 = mn1;

            uint32_t pA[8], pB[8];
            float ps0 = 0.f, ps1 = 0.f;
#pragma unroll
            for (int nt = 0; nt < 8; nt++) {
                float e0 = exp2f((s[nt][0] - m0) * LOG2E);
                float e1 = exp2f((s[nt][1] - m0) * LOG2E);
                float e2 = exp2f((s[nt][2] - m1) * LOG2E);
                float e3 = exp2f((s[nt][3] - m1) * LOG2E);
                ps0 += e0 + e1;
                ps1 += e2 + e3;
                pA[nt] = pack2(e0, e1);
                pB[nt] = pack2(e2, e3);
            }
            ps0 += __shfl_xor_sync(0xffffffffu, ps0, 1);
            ps0 += __shfl_xor_sync(0xffffffffu, ps0, 2);
            ps1 += __shfl_xor_sync(0xffffffffu, ps1, 1);
            ps1 += __shfl_xor_sync(0xffffffffu, ps1, 2);
            l0 = l0 * rc0 + ps0;
            l1 = l1 * rc1 + ps1;

            // rescale O only when some row max actually moved (exact identity
            // multiply by 1.0 skipped; common once the softcapped max saturates)
            if (!__all_sync(0xffffffffu, (rc0 == 1.f) && (rc1 == 1.f))) {
#pragma unroll
                for (int dt = 0; dt < 32; dt++) {
                    o[dt][0] *= rc0; o[dt][1] *= rc0;
                    o[dt][2] *= rc1; o[dt][3] *= rc1;
                }
            }

            // ---- PV: P in registers, V from smem ----
#pragma unroll
            for (int s4 = 0; s4 < 4; s4++) {
                uint32_t a[4];
                a[0] = pA[2 * s4];
                a[1] = pB[2 * s4];
                a[2] = pA[2 * s4 + 1];
                a[3] = pB[2 * s4 + 1];
#pragma unroll
                for (int dtp = 0; dtp < 16; dtp++) {
                    uint32_t b[4];
                    LDSM4(b, vBase + dtp * (16 * 144) + s4 * 32);
                    MMA_F16(o[2 * dtp],     a, b[0], b[1]);
                    MMA_F16(o[2 * dtp + 1], a, b[2], b[3]);
                }
            }
        }

        // ---- epilogue: fully warp-local ----
        float i0 = 1.f / l0, i1 = 1.f / l1;
        const int row0 = q0 + wm + grp;
#pragma unroll
        for (int dt = 0; dt < 32; dt++) {
            int col = h * HD + dt * 8 + 2 * qd;
            *(uint32_t*)&g_attn[(size_t)row0 * 2048 + col] =
                pack2(o[dt][0] * i0, o[dt][1] * i0);
            *(uint32_t*)&g_attn[(size_t)(row0 + 8) * 2048 + col] =
                pack2(o[dt][2] * i1, o[dt][3] * i1);
        }
    }
}

// ---------------------------------------------------------------------------
extern "C" void kernel_launch(void* const* d_in, const int* in_sizes, int n_in,
                              void* d_out, int out_size)
{
    const float* hs  = (const float*)d_in[0];
    // d_in[1] = attention_mask: pure causal (window >= S), recomputed in-kernel
    const void*  pos = d_in[2];
    const float* wq  = (const float*)d_in[3];
    const float* wk  = (const float*)d_in[4];
    const float* wv  = (const float*)d_in[5];
    const float* wo  = (const float*)d_in[6];
    float* out = (float*)d_out;

    __half *pq, *pk, *pvt, *pa, *pah, *pwqt, *pwkt, *pwvt, *pwot;
    cudaGetSymbolAddress((void**)&pq,   g_q);
    cudaGetSymbolAddress((void**)&pk,   g_k);
    cudaGetSymbolAddress((void**)&pvt,  g_vt);
    cudaGetSymbolAddress((void**)&pa,   g_attn);
    cudaGetSymbolAddress((void**)&pah,  g_ah);
    cudaGetSymbolAddress((void**)&pwqt, g_wqt);
    cudaGetSymbolAddress((void**)&pwkt, g_wkt);
    cudaGetSymbolAddress((void**)&pwvt, g_wvt);
    cudaGetSymbolAddress((void**)&pwot, g_wot);

    cudaFuncSetAttribute(gemm_h_kernel,
                         cudaFuncAttributeMaxDynamicSharedMemorySize, GH_SMEM);
    cudaFuncSetAttribute(attn_h_kernel,
                         cudaFuncAttributeMaxDynamicSharedMemorySize, ATTN_SMEM);

    const int n8 = (S_LEN * 2048) / 8;
    dim3 tb(32, 8);

    // prepasses
    invd_kernel<<<1, 128>>>();
    tohalf_kernel<<<(n8 + 255) / 256, 256>>>(hs, pah, n8);
    thalf_all_kernel<<<dim3(192, 64), tb>>>(wq, wk, wv, wo,
                                            pwqt, pwkt, pwvt, pwot);
    // fused QKV projection (3-stage pipelined fp16 GEMM)
    gemm_h_kernel<<<dim3(32, 32), 256, GH_SMEM>>>(
        pah, pwqt, pwkt, pwvt, pq, pk, pvt, nullptr, 1);
    // RoPE (+ fold attention scaling into q)
    rope_kernel<<<(S_LEN * 128) / 256, 256>>>(pos);
    // causal flash attention with tanh softcap (FA2 + rescale-skip)
    attn_h_kernel<<<dim3(16, NH), 256, ATTN_SMEM>>>();
    // output projection
    gemm_h_kernel<<<dim3(16, 32), 256, GH_SMEM>>>(
        pa, pwot, nullptr, nullptr, nullptr, nullptr, nullptr, out, 0);
}

// round 17
// speedup vs baseline: 1.0281x; 1.0281x over previous
#include <cuda_runtime.h>
#include <cuda_fp16.h>
#include <math.h>
#include <stdint.h>

#define S_LEN 4096
#define NH 8
#define NKV 4
#define HD 256

// ---------------- scratch (allocation-free device globals) -----------------
__device__ __half g_q[(size_t)NH * S_LEN * HD];     // [h][s][d] fp16
__device__ __half g_k[(size_t)NKV * S_LEN * HD];    // [h][s][d] fp16
__device__ __half g_vt[(size_t)NKV * HD * S_LEN];   // [h][d][s] fp16 (transposed)
__device__ __half g_attn[(size_t)S_LEN * 2048];     // [s][h*HD+d] fp16
__device__ __half g_ah[(size_t)S_LEN * 2048];       // hs fp16
__device__ __half g_wqt[(size_t)2048 * 2048];       // weights [N][K] fp16
__device__ __half g_wkt[(size_t)1024 * 2048];
__device__ __half g_wvt[(size_t)1024 * 2048];
__device__ __half g_wot[(size_t)2048 * 2048];
__device__ double g_invd[128];                      // rope inv_freq table

__device__ __forceinline__ uint32_t cvta_shared(const void* p) {
    uint32_t a;
    asm("{ .reg .u64 t; cvta.to.shared.u64 t, %1; cvt.u32.u64 %0, t; }"
        : "=r"(a) : "l"(p));
    return a;
}

__device__ __forceinline__ void cp16(uint32_t dst, const void* src) {
    asm volatile("cp.async.cg.shared.global [%0], [%1], 16;"
                 :: "r"(dst), "l"(src));
}
#define CP_COMMIT() asm volatile("cp.async.commit_group;")
#define CP_WAIT0()  asm volatile("cp.async.wait_group 0;")
#define CP_WAIT1()  asm volatile("cp.async.wait_group 1;")

#define MMA_F16(C, A, B0, B1)                                               \
    asm volatile(                                                           \
        "mma.sync.aligned.m16n8k16.row.col.f32.f16.f16.f32 "                \
        "{%0,%1,%2,%3}, {%4,%5,%6,%7}, {%8,%9}, {%0,%1,%2,%3};"             \
        : "+f"((C)[0]), "+f"((C)[1]), "+f"((C)[2]), "+f"((C)[3])            \
        : "r"((A)[0]), "r"((A)[1]), "r"((A)[2]), "r"((A)[3]),               \
          "r"(B0), "r"(B1))

#define LDSM4(R, addr)                                                      \
    asm volatile("ldmatrix.sync.aligned.m8n8.x4.shared.b16 "                \
                 "{%0,%1,%2,%3}, [%4];"                                     \
        : "=r"((R)[0]), "=r"((R)[1]), "=r"((R)[2]), "=r"((R)[3])            \
        : "r"(addr))

__device__ __forceinline__ uint32_t pack2(float a, float b) {
    __half2 h = __floats2half2_rn(a, b);
    return *(uint32_t*)&h;
}

// ---------------------------------------------------------------------------
// Prepass: fp32 -> fp16 (rn), 8 elems/thread. Block 0 also fills the rope
// inv_freq table (runs before rope in-stream).
// ---------------------------------------------------------------------------
__global__ void tohalf_kernel(const float* __restrict__ src,
                              __half* __restrict__ dst, int n8)
{
    if (blockIdx.x == 0 && threadIdx.x < 128)
        g_invd[threadIdx.x] =
            exp(-(double)threadIdx.x * (9.210340371976184 / 128.0));
    int i = blockIdx.x * blockDim.x + threadIdx.x;
    if (i >= n8) return;
    float4 a = ((const float4*)src)[i * 2];
    float4 b = ((const float4*)src)[i * 2 + 1];
    uint4 o;
    o.x = pack2(a.x, a.y); o.y = pack2(a.z, a.w);
    o.z = pack2(b.x, b.y); o.w = pack2(b.z, b.w);
    ((uint4*)dst)[i] = o;
}

__global__ void thalf_all_kernel(const float* __restrict__ wq,
                                 const float* __restrict__ wk,
                                 const float* __restrict__ wv,
                                 const float* __restrict__ wo,
                                 __half* __restrict__ wqt,
                                 __half* __restrict__ wkt,
                                 __half* __restrict__ wvt,
                                 __half* __restrict__ wot)
{
    __shared__ float t[32][33];
    const int bx = blockIdx.x;
    const float* W;
    __half* Wt;
    int N, n0;
    if (bx < 64)       { W = wq; Wt = wqt; N = 2048; n0 = bx * 32; }
    else if (bx < 96)  { W = wk; Wt = wkt; N = 1024; n0 = (bx - 64) * 32; }
    else if (bx < 128) { W = wv; Wt = wvt; N = 1024; n0 = (bx - 96) * 32; }
    else               { W = wo; Wt = wot; N = 2048; n0 = (bx - 128) * 32; }
    const int k0 = blockIdx.y * 32;
    const int tx = threadIdx.x, ty = threadIdx.y;
#pragma unroll
    for (int j = 0; j < 4; j++)
        t[ty + 8 * j][tx] = W[(size_t)(k0 + ty + 8 * j) * N + n0 + tx];
    __syncthreads();
    const int nl = ty * 4 + (tx >> 3);
    const int kl = (tx & 7) * 4;
    uint2 o;
    o.x = pack2(t[kl + 0][nl], t[kl + 1][nl]);
    o.y = pack2(t[kl + 2][nl], t[kl + 3][nl]);
    *(uint2*)&Wt[(size_t)(n0 + nl) * 2048 + k0 + kl] = o;
}

// ---------------------------------------------------------------------------
// fp16 tensor-core GEMM, ldmatrix fragments, 3-stage cp.async pipeline with
// a SINGLE barrier per k-chunk (trailing barrier provably redundant with 3
// stages: iter i+1's loads hit stage (i+3)%3 == i%3, ordered by the top
// barrier of iter i+1 against iter i's compute).
// ---------------------------------------------------------------------------
#define GH_PLANE 18432                   // 128 rows * 144 B
#define GH_STAGE (2 * GH_PLANE)
#define GH_SMEM  (3 * GH_STAGE)          // 110592 B

__global__ __launch_bounds__(256, 2) void gemm_h_kernel(
    const __half* __restrict__ A,
    const __half* __restrict__ B0t, const __half* __restrict__ B1t,
    const __half* __restrict__ B2t,
    __half* __restrict__ Cq, __half* __restrict__ Ck, __half* __restrict__ Cvt,
    float* __restrict__ Cplain, int merged)
{
    extern __shared__ char gsm[];
    const uint32_t smem_base = cvta_shared(gsm);

    const int tid  = threadIdx.x;
    const int lane = tid & 31;
    const int wid  = tid >> 5;
    const int wm   = (wid & 3) * 32;
    const int wn   = (wid >> 2) * 64;
    const int bm   = blockIdx.y * 128;
    const int bn   = blockIdx.x * 128;
    const int grp  = lane >> 2;
    const int qd   = lane & 3;
    const int mi   = lane >> 3;
    const int r8   = lane & 7;

    const uint32_t aoff = (uint32_t)(wm + (mi & 1) * 8 + r8) * 144 + (mi >> 1) * 16;
    const uint32_t boff = (uint32_t)GH_PLANE +
                          (uint32_t)(wn + (mi >> 1) * 8 + r8) * 144 + (mi & 1) * 16;

    const __half* Bt;
    int nb, head = 0, colb0 = 0, region = 0;
    if (merged) {
        if (bn < 2048)      { Bt = B0t; nb = bn;        region = 0; }
        else if (bn < 3072) { Bt = B1t; nb = bn - 2048; region = 1; }
        else                { Bt = B2t; nb = bn - 3072; region = 2; }
        head = nb >> 8;
        colb0 = nb & 255;
    } else {
        Bt = B0t; nb = bn;
    }

    auto load_stage = [&](int chunk, int st) {
        const int k0 = chunk * 64;
        const uint32_t sb = smem_base + st * GH_STAGE;
#pragma unroll
        for (int p = 0; p < 4; p++) {
            int idx = tid + p * 256;
            int row = idx >> 3, c = idx & 7;
            cp16(sb + row * 144 + c * 16,
                 &A[(size_t)(bm + row) * 2048 + k0 + c * 8]);
            cp16(sb + GH_PLANE + row * 144 + c * 16,
                 &Bt[(size_t)(nb + row) * 2048 + k0 + c * 8]);
        }
        CP_COMMIT();
    };

    float c[2][8][4];
#pragma unroll
    for (int mf = 0; mf < 2; mf++)
#pragma unroll
        for (int nt = 0; nt < 8; nt++)
#pragma unroll
            for (int r = 0; r < 4; r++) c[mf][nt][r] = 0.f;

    load_stage(0, 0);
    load_stage(1, 1);

    int st = 0, ldst = 2;
    for (int i = 0; i < 32; i++) {
        if (i < 30) CP_WAIT1(); else CP_WAIT0();
        __syncthreads();               // single barrier per k-chunk
        if (i + 2 < 32) load_stage(i + 2, ldst);

        const uint32_t stb = smem_base + st * GH_STAGE;
#pragma unroll
        for (int s = 0; s < 4; s++) {
            uint32_t a[2][4];
            LDSM4(a[0], stb + aoff + s * 32);
            LDSM4(a[1], stb + aoff + 16 * 144 + s * 32);
#pragma unroll
            for (int ntp = 0; ntp < 4; ntp++) {
                uint32_t b[4];
                LDSM4(b, stb + boff + ntp * (16 * 144) + s * 32);
                MMA_F16(c[0][2 * ntp],     a[0], b[0], b[1]);
                MMA_F16(c[1][2 * ntp],     a[1], b[0], b[1]);
                MMA_F16(c[0][2 * ntp + 1], a[0], b[2], b[3]);
                MMA_F16(c[1][2 * ntp + 1], a[1], b[2], b[3]);
            }
        }
        st   = (st == 2)   ? 0 : st + 1;
        ldst = (ldst == 2) ? 0 : ldst + 1;
    }

    const int m0 = bm + wm + grp;
    const int n0 = wn + 2 * qd;
    if (merged) {
        if (region < 2) {
            __half* Cp = (region == 0) ? Cq : Ck;
            const size_t hbase = (size_t)head * ((size_t)S_LEN * HD) + colb0;
#pragma unroll
            for (int mf = 0; mf < 2; mf++)
#pragma unroll
                for (int nt = 0; nt < 8; nt++) {
                    int m = m0 + mf * 16;
                    int ncol = n0 + nt * 8;
                    *(uint32_t*)&Cp[hbase + (size_t)m * HD + ncol] =
                        pack2(c[mf][nt][0], c[mf][nt][1]);
                    *(uint32_t*)&Cp[hbase + (size_t)(m + 8) * HD + ncol] =
                        pack2(c[mf][nt][2], c[mf][nt][3]);
                }
        } else {
            const size_t vbase = (size_t)head * ((size_t)HD * S_LEN);
#pragma unroll
            for (int mf = 0; mf < 2; mf++)
#pragma unroll
                for (int nt = 0; nt < 8; nt++) {
                    int m = m0 + mf * 16;
                    int d = colb0 + n0 + nt * 8;
                    Cvt[vbase + (size_t)d * S_LEN + m]           = __float2half_rn(c[mf][nt][0]);
                    Cvt[vbase + (size_t)(d + 1) * S_LEN + m]     = __float2half_rn(c[mf][nt][1]);
                    Cvt[vbase + (size_t)d * S_LEN + m + 8]       = __float2half_rn(c[mf][nt][2]);
                    Cvt[vbase + (size_t)(d + 1) * S_LEN + m + 8] = __float2half_rn(c[mf][nt][3]);
                }
        }
    } else {
#pragma unroll
        for (int mf = 0; mf < 2; mf++)
#pragma unroll
            for (int nt = 0; nt < 8; nt++) {
                int m = m0 + mf * 16;
                int n = bn + n0 + nt * 8;
                *(float2*)&Cplain[(size_t)m * 2048 + n] =
                    make_float2(c[mf][nt][0], c[mf][nt][1]);
                *(float2*)&Cplain[(size_t)(m + 8) * 2048 + n] =
                    make_float2(c[mf][nt][2], c[mf][nt][3]);
            }
    }
}

// ---------------------------------------------------------------------------
// RoPE on fp16 q/k (table inv_freq, DMUL range reduction).
// ---------------------------------------------------------------------------
__global__ void rope_kernel(const void* __restrict__ pos_raw)
{
    int idx = blockIdx.x * blockDim.x + threadIdx.x;
    if (idx >= S_LEN * 128) return;
    int i = idx & 127;
    int s = idx >> 7;

    const int* p32 = (const int*)pos_raw;
    long long pll = (p32[1] == 0) ? ((const long long*)pos_raw)[s]
                                  : (long long)p32[s];
    float p = (float)pll;

    float f = (float)((double)p * g_invd[i]);
    const double TWO_PI     = 6.283185307179586476925287;
    const double INV_TWO_PI = 0.15915494309189533576888;
    double r = (double)f;
    r -= TWO_PI * floor(r * INV_TWO_PI);
    float sv = sinf((float)r);
    float cv = cosf((float)r);

#pragma unroll
    for (int h = 0; h < NH; h++) {
        __half* base = g_q + ((size_t)h * S_LEN + s) * HD;
        float x1 = __half2float(base[i]), x2 = __half2float(base[i + 128]);
        base[i]       = __float2half_rn((x1 * cv - x2 * sv) * 0.0625f);
        base[i + 128] = __float2half_rn((x2 * cv + x1 * sv) * 0.0625f);
    }
#pragma unroll
    for (int h = 0; h < NKV; h++) {
        __half* base = g_k + ((size_t)h * S_LEN + s) * HD;
        float x1 = __half2float(base[i]), x2 = __half2float(base[i + 128]);
        base[i]       = __float2half_rn(x1 * cv - x2 * sv);
        base[i + 128] = __float2half_rn(x2 * cv + x1 * sv);
    }
}

// ---------------------------------------------------------------------------
// fp16 flash attention, warp-local rows (FA2 style) — R15 proven structure.
// 8 warps x 16 q-rows; P in registers; single barrier per k-block;
// double-buffered K/V. Grid (16, 8) paired q-tiles, 66 k-blocks.
// ---------------------------------------------------------------------------
#define A2OFF_Q   0
#define A2_QSZ    (128 * 528)             // 67584
#define A2_KSZ    (64 * 528)              // 33792
#define A2_VSZ    (256 * 144)             // 36864
#define A2_STG(st) (A2_QSZ + (st) * (A2_KSZ + A2_VSZ))
#define ATTN_SMEM (A2_QSZ + 2 * (A2_KSZ + A2_VSZ))   // 208896

__global__ __launch_bounds__(256) void attn_h_kernel()
{
    extern __shared__ char smn[];
    const uint32_t sb = cvta_shared(smn);

    const int h  = blockIdx.y;
    const int hk = h >> 1;
    const int tid  = threadIdx.x;
    const int lane = tid & 31;
    const int wid  = tid >> 5;
    const int wm   = wid * 16;
    const int grp  = lane >> 2;
    const int qd   = lane & 3;
    const int mi   = lane >> 3;
    const int r8   = lane & 7;

    const uint32_t qBase = sb + A2OFF_Q +
        (uint32_t)(wm + (mi & 1) * 8 + r8) * 528 + (mi >> 1) * 16;
    const uint32_t kLane = (uint32_t)((mi >> 1) * 8 + r8) * 528 + (mi & 1) * 16;
    const uint32_t vLane = (uint32_t)((mi >> 1) * 8 + r8) * 144 + (mi & 1) * 16;

    const __half* Qh  = g_q  + (size_t)h  * S_LEN * HD;
    const __half* Kh  = g_k  + (size_t)hk * S_LEN * HD;
    const __half* Vth = g_vt + (size_t)hk * HD * S_LEN;

    const float LOG2E = 1.4426950408889634f;

    auto load_kv = [&](int k0, int st) {
        const uint32_t kb = sb + A2_STG(st);
        const uint32_t vb = kb + A2_KSZ;
#pragma unroll
        for (int p = 0; p < 8; p++) {
            int idx = tid + p * 256;
            int row = idx >> 5, cc = idx & 31;
            cp16(kb + row * 528 + cc * 16,
                 &Kh[(size_t)(k0 + row) * HD + cc * 8]);
        }
#pragma unroll
        for (int p = 0; p < 8; p++) {
            int idx = tid + p * 256;
            int row = idx >> 3, cc = idx & 7;
            cp16(vb + row * 144 + cc * 16,
                 &Vth[(size_t)row * S_LEN + k0 + cc * 8]);
        }
        CP_COMMIT();
    };

    for (int half = 0; half < 2; half++) {
        const int qt = half ? (31 - blockIdx.x) : blockIdx.x;
        const int q0 = qt * 128;
        const int nkb = 2 * qt + 2;

        __syncthreads();
#pragma unroll
        for (int p = 0; p < 16; p++) {
            int idx = tid + p * 256;
            int row = idx >> 5, cc = idx & 31;
            cp16(sb + A2OFF_Q + row * 528 + cc * 16,
                 &Qh[(size_t)(q0 + row) * HD + cc * 8]);
        }
        CP_COMMIT();
        load_kv(0, 0);

        float m0 = -3.0e38f, m1 = -3.0e38f, l0 = 0.f, l1 = 0.f;
        float o[32][4];
#pragma unroll
        for (int dt = 0; dt < 32; dt++)
#pragma unroll
            for (int r = 0; r < 4; r++) o[dt][r] = 0.f;

        for (int kb = 0; kb < nkb; kb++) {
            const int st = kb & 1;
            const int k0 = kb * 64;
            CP_WAIT0();
            __syncthreads();
            if (kb + 1 < nkb) load_kv(k0 + 64, st ^ 1);

            const uint32_t kBase = sb + A2_STG(st) + kLane;
            const uint32_t vBase = sb + A2_STG(st) + A2_KSZ + vLane;

            // ---- QK: 16 rows x 64 cols ----
            float s[8][4];
#pragma unroll
            for (int nt = 0; nt < 8; nt++)
#pragma unroll
                for (int r = 0; r < 4; r++) s[nt][r] = 0.f;
#pragma unroll 4
            for (int ks = 0; ks < 16; ks++) {
                uint32_t a[4];
                LDSM4(a, qBase + ks * 32);
#pragma unroll
                for (int t = 0; t < 4; t++) {
                    uint32_t b[4];
                    LDSM4(b, kBase + t * (16 * 528) + ks * 32);
                    MMA_F16(s[2 * t],     a, b[0], b[1]);
                    MMA_F16(s[2 * t + 1], a, b[2], b[3]);
                }
            }

            // ---- softcap + causal + warp-local softmax ----
            float lm0 = -3.0e38f, lm1 = -3.0e38f;
#pragma unroll
            for (int nt = 0; nt < 8; nt++)
#pragma unroll
                for (int cc = 0; cc < 4; cc++) {
                    float x = s[nt][cc];
                    float u = x * 0.02f;
                    float u2 = u * u;
                    float val = x * (1.f + u2 * (-0.333333333f +
                                  u2 * (0.133333333f + u2 * -0.053968254f)));
                    if (u2 > 0.1225f) val = 50.f * tanhf(u);
                    int kcol = k0 + nt * 8 + 2 * qd + (cc & 1);
                    int qrow = q0 + wm + grp + (cc >> 1) * 8;
                    if (kcol > qrow) val = -1.0e30f;
                    s[nt][cc] = val;
                    if (cc < 2) lm0 = fmaxf(lm0, val);
                    else        lm1 = fmaxf(lm1, val);
                }
            lm0 = fmaxf(lm0, __shfl_xor_sync(0xffffffffu, lm0, 1));
            lm0 = fmaxf(lm0, __shfl_xor_sync(0xffffffffu, lm0, 2));
            lm1 = fmaxf(lm1, __shfl_xor_sync(0xffffffffu, lm1, 1));
            lm1 = fmaxf(lm1, __shfl_xor_sync(0xffffffffu, lm1, 2));
            float mn0 = fmaxf(m0, lm0), mn1 = fmaxf(m1, lm1);
            float rc0 = exp2f((m0 - mn0) * LOG2E);
            float rc1 = exp2f((m1 - mn1) * LOG2E);
            m0 = mn0; m1 = mn1;

            uint32_t pA[8], pB[8];
            float ps0 = 0.f, ps1 = 0.f;
#pragma unroll
            for (int nt = 0; nt < 8; nt++) {
                float e0 = exp2f((s[nt][0] - m0) * LOG2E);
                float e1 = exp2f((s[nt][1] - m0) * LOG2E);
                float e2 = exp2f((s[nt][2] - m1) * LOG2E);
                float e3 = exp2f((s[nt][3] - m1) * LOG2E);
                ps0 += e0 + e1;
                ps1 += e2 + e3;
                pA[nt] = pack2(e0, e1);
                pB[nt] = pack2(e2, e3);
            }
            ps0 += __shfl_xor_sync(0xffffffffu, ps0, 1);
            ps0 += __shfl_xor_sync(0xffffffffu, ps0, 2);
            ps1 += __shfl_xor_sync(0xffffffffu, ps1, 1);
            ps1 += __shfl_xor_sync(0xffffffffu, ps1, 2);
            l0 = l0 * rc0 + ps0;
            l1 = l1 * rc1 + ps1;

#pragma unroll
            for (int dt = 0; dt < 32; dt++) {
                o[dt][0] *= rc0; o[dt][1] *= rc0;
                o[dt][2] *= rc1; o[dt][3] *= rc1;
            }

            // ---- PV: P in registers, V from smem ----
#pragma unroll
            for (int s4 = 0; s4 < 4; s4++) {
                uint32_t a[4];
                a[0] = pA[2 * s4];
                a[1] = pB[2 * s4];
                a[2] = pA[2 * s4 + 1];
                a[3] = pB[2 * s4 + 1];
#pragma unroll
                for (int dtp = 0; dtp < 16; dtp++) {
                    uint32_t b[4];
                    LDSM4(b, vBase + dtp * (16 * 144) + s4 * 32);
                    MMA_F16(o[2 * dtp],     a, b[0], b[1]);
                    MMA_F16(o[2 * dtp + 1], a, b[2], b[3]);
                }
            }
        }

        // ---- epilogue: fully warp-local ----
        float i0 = 1.f / l0, i1 = 1.f / l1;
        const int row0 = q0 + wm + grp;
#pragma unroll
        for (int dt = 0; dt < 32; dt++) {
            int col = h * HD + dt * 8 + 2 * qd;
            *(uint32_t*)&g_attn[(size_t)row0 * 2048 + col] =
                pack2(o[dt][0] * i0, o[dt][1] * i0);
            *(uint32_t*)&g_attn[(size_t)(row0 + 8) * 2048 + col] =
                pack2(o[dt][2] * i1, o[dt][3] * i1);
        }
    }
}

// ---------------------------------------------------------------------------
extern "C" void kernel_launch(void* const* d_in, const int* in_sizes, int n_in,
                              void* d_out, int out_size)
{
    const float* hs  = (const float*)d_in[0];
    // d_in[1] = attention_mask: pure causal (window >= S), recomputed in-kernel
    const void*  pos = d_in[2];
    const float* wq  = (const float*)d_in[3];
    const float* wk  = (const float*)d_in[4];
    const float* wv  = (const float*)d_in[5];
    const float* wo  = (const float*)d_in[6];
    float* out = (float*)d_out;

    __half *pq, *pk, *pvt, *pa, *pah, *pwqt, *pwkt, *pwvt, *pwot;
    cudaGetSymbolAddress((void**)&pq,   g_q);
    cudaGetSymbolAddress((void**)&pk,   g_k);
    cudaGetSymbolAddress((void**)&pvt,  g_vt);
    cudaGetSymbolAddress((void**)&pa,   g_attn);
    cudaGetSymbolAddress((void**)&pah,  g_ah);
    cudaGetSymbolAddress((void**)&pwqt, g_wqt);
    cudaGetSymbolAddress((void**)&pwkt, g_wkt);
    cudaGetSymbolAddress((void**)&pwvt, g_wvt);
    cudaGetSymbolAddress((void**)&pwot, g_wot);

    cudaFuncSetAttribute(gemm_h_kernel,
                         cudaFuncAttributeMaxDynamicSharedMemorySize, GH_SMEM);
    cudaFuncSetAttribute(attn_h_kernel,
                         cudaFuncAttributeMaxDynamicSharedMemorySize, ATTN_SMEM);

    const int n8 = (S_LEN * 2048) / 8;
    dim3 tb(32, 8);

    // prepasses (tohalf also fills the rope inv_freq table)
    tohalf_kernel<<<(n8 + 255) / 256, 256>>>(hs, pah, n8);
    thalf_all_kernel<<<dim3(192, 64), tb>>>(wq, wk, wv, wo,
                                            pwqt, pwkt, pwvt, pwot);
    // fused QKV projection (3-stage pipelined fp16 GEMM, 1 barrier/chunk)
    gemm_h_kernel<<<dim3(32, 32), 256, GH_SMEM>>>(
        pah, pwqt, pwkt, pwvt, pq, pk, pvt, nullptr, 1);
    // RoPE (+ fold attention scaling into q)
    rope_kernel<<<(S_LEN * 128) / 256, 256>>>(pos);
    // causal flash attention with tanh softcap (FA2 warp-local, R15 proven)
    attn_h_kernel<<<dim3(16, NH), 256, ATTN_SMEM>>>();
    // output projection
    gemm_h_kernel<<<dim3(16, 32), 256, GH_SMEM>>>(
        pa, pwot, nullptr, nullptr, nullptr, nullptr, nullptr, out, 0);
}